// round 15
// baseline (speedup 1.0000x reference)
#include <cuda_runtime.h>
#include <math.h>

#define RPB 3       // rows per block (2 warps per row: one per head)
#define THREADS 192

// ---------------- precomputed tables ----------------
// One 128B line per (t,c): 8 float4 parts, each a ready-made 16B shared store:
//  p0=(q0,q1,q2,0) p1=(q3,q4,q5,0)   -> Q[t][0..3], Q[t][4..7]
//  p2=(k0,k1,k2,0) p3=(k3,k4,k5,0)   -> K[t][0..3], K[t][4..7]
//  p4=(v0,v1,v2,0) p5=(v3,v4,v5,0)   -> V[t][0..3], V[t][4..7]
//  p6=(x0..x3)     p7=(x4,x5,0,0)    -> X[t][0..3], X[t][4..7]
__device__ __align__(128) float g_TAB[34 * 14 * 32];
// Packed, 16B-aligned epilogue constants (200 floats = 50 float4)
__device__ __align__(16) float g_packed[200];

__device__ __forceinline__ int flatmap(int p) {
    if (p < 10) return p;
    if (p == 10) return 11;
    if (p < 21) return p - 11;
    if (p == 21) return 12;
    if (p < 33) { int z = p - 22; return z < 10 ? z : 10; }
    return 13;
}

__global__ void setup_kernel(const float* __restrict__ tok_emb, const float* __restrict__ pos_params,
                             const float* __restrict__ z10, const float* __restrict__ spec,
                             const float* __restrict__ wq, const float* __restrict__ wk,
                             const float* __restrict__ wv,
                             const float* __restrict__ ln1_g, const float* __restrict__ ln1_b,
                             const float* __restrict__ wo, const float* __restrict__ ln2_g,
                             const float* __restrict__ ln2_b,
                             const float* __restrict__ lnf_g, const float* __restrict__ lnf_b,
                             const float* __restrict__ fw1, const float* __restrict__ fb1,
                             const float* __restrict__ fw2, const float* __restrict__ fb2,
                             const float* __restrict__ head_w)
{
    int tid = threadIdx.x;

    if (tid < 200) {
        float v = 0.f;
        if (tid < 48) {
            int i = tid >> 3, j = tid & 7;
            v = (j < 6) ? wo[i * 6 + j] : 0.f;
        } else if (tid < 60) {
            int u = tid - 48; int j = u >> 1, m = u & 1;
            v = ln2_g[j] * fw1[j * 2 + m];
        } else if (tid < 62) {
            int m = tid - 60; float s = 0.f;
            for (int j = 0; j < 6; j++) s += ln2_g[j] * fw1[j * 2 + m];
            v = s;
        } else if (tid < 64) {
            int m = tid - 62; float s = fb1[m];
            for (int j = 0; j < 6; j++) s += ln2_b[j] * fw1[j * 2 + m];
            v = s;
        } else if (tid < 80) {
            int u = tid - 64; int m = u >> 3, j = u & 7;
            v = (j < 6) ? fw2[m * 6 + j] : 0.f;
        } else if (tid < 88) {
            int j = tid - 80;
            v = (j < 6) ? fb2[j] : 0.f;
        } else {
            int u = tid - 88; int n = u >> 3, j = u & 7;
            if (j < 6) {
                float W = head_w[j * 3 + 0] * tok_emb[n * 3 + 0]
                        + head_w[j * 3 + 1] * tok_emb[n * 3 + 1]
                        + head_w[j * 3 + 2] * tok_emb[n * 3 + 2];
                v = lnf_g[j] * W;
            } else {
                const float* gb = (j == 6) ? lnf_g : lnf_b;
                float s = 0.f;
                for (int jj = 0; jj < 6; jj++) {
                    float W = head_w[jj * 3 + 0] * tok_emb[n * 3 + 0]
                            + head_w[jj * 3 + 1] * tok_emb[n * 3 + 1]
                            + head_w[jj * 3 + 2] * tok_emb[n * 3 + 2];
                    s += gb[jj] * W;
                }
                v = s;
            }
        }
        g_packed[tid] = v;
    }

    for (int i = tid; i < 34 * 14; i += blockDim.x) {
        int t = i / 14, c = i % 14;
        int f = flatmap(t);
        float p0, p1, p2;
        if (f < 10) {
            float amp = pos_params[0], ph = pos_params[1], sl = pos_params[2], of = pos_params[3];
            float ang = 0.62831853071795864f * (float)f + ph;
            p0 = amp * cosf(ang);
            p1 = amp * sinf(ang);
            p2 = sl * (float)f + of;
        } else if (f == 10) {
            p0 = z10[0]; p1 = z10[1]; p2 = z10[2];
        } else {
            int s = f - 11;
            p0 = spec[s * 3 + 0]; p1 = spec[s * 3 + 1]; p2 = spec[s * 3 + 2];
        }
        float x[6] = { tok_emb[c * 3 + 0], tok_emb[c * 3 + 1], tok_emb[c * 3 + 2], p0, p1, p2 };
        float mu = 0.f;
        #pragma unroll
        for (int j = 0; j < 6; j++) mu += x[j];
        mu *= (1.f / 6.f);
        float var = 0.f;
        #pragma unroll
        for (int j = 0; j < 6; j++) { float d = x[j] - mu; var += d * d; }
        var *= (1.f / 6.f);
        float rs = rsqrtf(var + 1e-5f);
        float h[6];
        #pragma unroll
        for (int j = 0; j < 6; j++) h[j] = (x[j] - mu) * rs * ln1_g[j] + ln1_b[j];

        const float QS = 1.4426950408889634f / 1.7320508075688772f;  // log2(e)/sqrt(3)
        float qv[6], kv[6], vv[6];
        #pragma unroll
        for (int j = 0; j < 6; j++) {
            qv[j] = (h[3] * wq[j] + h[4] * wq[6 + j] + h[5] * wq[12 + j]) * QS;
            kv[j] =  h[3] * wk[j] + h[4] * wk[6 + j] + h[5] * wk[12 + j];
            vv[j] =  h[0] * wv[j] + h[1] * wv[6 + j] + h[2] * wv[12 + j];
        }
        float* T = &g_TAB[i * 32];
        T[0]  = qv[0]; T[1]  = qv[1]; T[2]  = qv[2]; T[3]  = 0.f;
        T[4]  = qv[3]; T[5]  = qv[4]; T[6]  = qv[5]; T[7]  = 0.f;
        T[8]  = kv[0]; T[9]  = kv[1]; T[10] = kv[2]; T[11] = 0.f;
        T[12] = kv[3]; T[13] = kv[4]; T[14] = kv[5]; T[15] = 0.f;
        T[16] = vv[0]; T[17] = vv[1]; T[18] = vv[2]; T[19] = 0.f;
        T[20] = vv[3]; T[21] = vv[4]; T[22] = vv[5]; T[23] = 0.f;
        T[24] = x[0];  T[25] = x[1];  T[26] = x[2];  T[27] = x[3];
        T[28] = x[4];  T[29] = x[5];  T[30] = 0.f;   T[31] = 0.f;
    }
}

// ---------------- main kernel ----------------

struct __align__(16) RowShm {
    float Q[36][8];   // [t][4h+0..2] = q head h (rows 34-35 pad)
    float K[36][8];   // [t][4h+0..2] = k head h (rows 34-35 zeroed)
    float V[36][8];   // [t][4h+0..2] = v head h (rows 34-35 zeroed)
    float X[36][8];   // [t][0..5]
    float O[34][8];   // [t][4h+0..2] = attention out head h
    // Q+K region (576 floats) reused as the 476-float logits buffer in the epilogue
};

__device__ __forceinline__ float ex2f(float x) {
    float y;
    asm("ex2.approx.ftz.f32 %0, %1;" : "=f"(y) : "f"(x));
    return y;
}
__device__ __forceinline__ float rcpf(float x) {
    float y;
    asm("rcp.approx.ftz.f32 %0, %1;" : "=f"(y) : "f"(x));
    return y;
}
// Abramowitz-Stegun 7.1.26 erf approximation, |abs err| <= 1.5e-7
__device__ __forceinline__ float erf_fast(float x) {
    float ax = fabsf(x);
    float t = rcpf(1.f + 0.3275911f * ax);
    float y = t * (0.254829592f + t * (-0.284496736f + t * (1.421413741f
            + t * (-1.453152027f + t * 1.061405429f))));
    float e = ex2f(-1.4426950408889634f * ax * ax);
    float r = 1.f - y * e;
    return copysignf(r, x);
}

// Single causal-attention task for query t, head h; per-key broadcast float4 loads,
// keys processed in pairs to bound live registers.
__device__ __forceinline__ void attn_one(RowShm& S, int h, int t) {
    int qb = 4 * h;
    float4 q = *(const float4*)&S.Q[t][qb];
    float l = 0.f, a0 = 0.f, a1 = 0.f, a2 = 0.f;
    int nbf = t >> 2;   // full 4-key blocks (no masking)
    #pragma unroll 1
    for (int b = 0; b < nbf; b++) {
        int k0 = b << 2;
        {
            float4 ka = *(const float4*)&S.K[k0 + 0][qb];
            float4 kb = *(const float4*)&S.K[k0 + 1][qb];
            float4 va = *(const float4*)&S.V[k0 + 0][qb];
            float4 vb = *(const float4*)&S.V[k0 + 1][qb];
            float p0 = ex2f(q.x * ka.x + q.y * ka.y + q.z * ka.z);
            float p1 = ex2f(q.x * kb.x + q.y * kb.y + q.z * kb.z);
            l  += p0 + p1;
            a0 += p0 * va.x + p1 * vb.x;
            a1 += p0 * va.y + p1 * vb.y;
            a2 += p0 * va.z + p1 * vb.z;
        }
        {
            float4 ka = *(const float4*)&S.K[k0 + 2][qb];
            float4 kb = *(const float4*)&S.K[k0 + 3][qb];
            float4 va = *(const float4*)&S.V[k0 + 2][qb];
            float4 vb = *(const float4*)&S.V[k0 + 3][qb];
            float p0 = ex2f(q.x * ka.x + q.y * ka.y + q.z * ka.z);
            float p1 = ex2f(q.x * kb.x + q.y * kb.y + q.z * kb.z);
            l  += p0 + p1;
            a0 += p0 * va.x + p1 * vb.x;
            a1 += p0 * va.y + p1 * vb.y;
            a2 += p0 * va.z + p1 * vb.z;
        }
    }
    // masked tail: keys 4*nbf .. t (pad rows 34-35 are zeroed)
    {
        int k0 = nbf << 2;
        int rem = t & 3;
        {
            float4 ka = *(const float4*)&S.K[k0 + 0][qb];
            float4 kb = *(const float4*)&S.K[k0 + 1][qb];
            float4 va = *(const float4*)&S.V[k0 + 0][qb];
            float4 vb = *(const float4*)&S.V[k0 + 1][qb];
            float p0 = ex2f(q.x * ka.x + q.y * ka.y + q.z * ka.z);
            float p1 = ex2f(q.x * kb.x + q.y * kb.y + q.z * kb.z);
            if (rem < 1) p1 = 0.f;
            l  += p0 + p1;
            a0 += p0 * va.x + p1 * vb.x;
            a1 += p0 * va.y + p1 * vb.y;
            a2 += p0 * va.z + p1 * vb.z;
        }
        {
            float4 ka = *(const float4*)&S.K[k0 + 2][qb];
            float4 kb = *(const float4*)&S.K[k0 + 3][qb];
            float4 va = *(const float4*)&S.V[k0 + 2][qb];
            float4 vb = *(const float4*)&S.V[k0 + 3][qb];
            float p2 = ex2f(q.x * ka.x + q.y * ka.y + q.z * ka.z);
            float p3 = ex2f(q.x * kb.x + q.y * kb.y + q.z * kb.z);
            if (rem < 2) p2 = 0.f;
            if (rem < 3) p3 = 0.f;
            l  += p2 + p3;
            a0 += p2 * va.x + p3 * vb.x;
            a1 += p2 * va.y + p3 * vb.y;
            a2 += p2 * va.z + p3 * vb.z;
        }
    }
    float inv = rcpf(l);
    *(float4*)&S.O[t][qb] = make_float4(a0 * inv, a1 * inv, a2 * inv, 0.f);
}

// Per-position epilogue; constants read via float4, logits staged as float2 pairs.
__device__ __forceinline__ void epilogue_pos(RowShm& R, const float* cw, int t) {
    const float4* c4 = (const float4*)cw;
    float4 xa = *(const float4*)&R.X[t][0];
    float2 xb = *(const float2*)&R.X[t][4];
    float4 oa = *(const float4*)&R.O[t][0];
    float4 ob = *(const float4*)&R.O[t][4];
    float o[6] = { oa.x, oa.y, oa.z, ob.x, ob.y, ob.z };

    float y0 = xa.x, y1 = xa.y, y2 = xa.z, y3 = xa.w, y4 = xb.x, y5 = xb.y;
    #pragma unroll
    for (int i = 0; i < 6; i++) {
        float4 lo = c4[2 * i], hi = c4[2 * i + 1];
        y0 += o[i] * lo.x; y1 += o[i] * lo.y; y2 += o[i] * lo.z; y3 += o[i] * lo.w;
        y4 += o[i] * hi.x; y5 += o[i] * hi.y;
    }

    float mu = (y0 + y1 + y2 + y3 + y4 + y5) * (1.f / 6.f);
    float var = (y0 - mu) * (y0 - mu) + (y1 - mu) * (y1 - mu) + (y2 - mu) * (y2 - mu)
              + (y3 - mu) * (y3 - mu) + (y4 - mu) * (y4 - mu) + (y5 - mu) * (y5 - mu);
    float rs = rsqrtf(var * (1.f / 6.f) + 1e-5f);

    float4 fa = c4[12], fb = c4[13], fc = c4[14];
    float dot0 = y0 * fa.x + y1 * fa.z + y2 * fb.x + y3 * fb.z + y4 * fc.x + y5 * fc.z;
    float dot1 = y0 * fa.y + y1 * fa.w + y2 * fb.y + y3 * fb.w + y4 * fc.y + y5 * fc.w;
    float4 cb = c4[15];
    float f0 = rs * (dot0 - mu * cb.x) + cb.z;
    float f1 = rs * (dot1 - mu * cb.y) + cb.w;
    float g0 = 0.5f * f0 * (1.f + erf_fast(f0 * 0.70710678118654752f));
    float g1 = 0.5f * f1 * (1.f + erf_fast(f1 * 0.70710678118654752f));

    float4 r0lo = c4[16], r0hi = c4[17], r1lo = c4[18], r1hi = c4[19];
    float4 b2lo = c4[20], b2hi = c4[21];
    float z0 = y0 + g0 * r0lo.x + g1 * r1lo.x + b2lo.x;
    float z1 = y1 + g0 * r0lo.y + g1 * r1lo.y + b2lo.y;
    float z2 = y2 + g0 * r0lo.z + g1 * r1lo.z + b2lo.z;
    float z3 = y3 + g0 * r0lo.w + g1 * r1lo.w + b2lo.w;
    float z4 = y4 + g0 * r0hi.x + g1 * r1hi.x + b2hi.x;
    float z5 = y5 + g0 * r0hi.y + g1 * r1hi.y + b2hi.y;

    float mu2 = (z0 + z1 + z2 + z3 + z4 + z5) * (1.f / 6.f);
    float var2 = (z0 - mu2) * (z0 - mu2) + (z1 - mu2) * (z1 - mu2) + (z2 - mu2) * (z2 - mu2)
               + (z3 - mu2) * (z3 - mu2) + (z4 - mu2) * (z4 - mu2) + (z5 - mu2) * (z5 - mu2);
    float rs2 = rsqrtf(var2 * (1.f / 6.f) + 1e-5f);

    float2* Lp2 = (float2*)(&R.Q[0][0] + t * 14);
    #pragma unroll
    for (int n = 0; n < 14; n += 2) {
        float4 w0 = c4[22 + 2 * n], w1 = c4[23 + 2 * n];
        float4 u0 = c4[24 + 2 * n], u1 = c4[25 + 2 * n];
        float da = z0 * w0.x + z1 * w0.y + z2 * w0.z + z3 * w0.w + z4 * w1.x + z5 * w1.y;
        float db = z0 * u0.x + z1 * u0.y + z2 * u0.z + z3 * u0.w + z4 * u1.x + z5 * u1.y;
        float la = rs2 * (da - mu2 * w1.z) + w1.w;
        float lb = rs2 * (db - mu2 * u1.z) + u1.w;
        Lp2[n >> 1] = make_float2(la, lb);
    }
}

__global__ void __launch_bounds__(THREADS, 8)
fwd_kernel(const int* __restrict__ idx, float* __restrict__ out, int nrows)
{
    __shared__ RowShm shm[RPB];
    __shared__ __align__(16) float cw[200];

    int tid = threadIdx.x;
    for (int i = tid; i < 200; i += THREADS) cw[i] = g_packed[i];

    int w = tid >> 5, lane = tid & 31;
    int r = w >> 1;            // local row 0..RPB-1
    int sub = w & 1;           // head / gather-half
    int row = blockIdx.x * RPB + r;
    bool rowActive = row < nrows;
    RowShm& S = shm[r];

    // ---- phase 2: cooperative line-aligned gather (2 warps, 17 entries each) ----
    if (rowActive) {
        // zero pad rows 34-35: sub0 -> K, sub1 -> V
        if (lane < 4) {
            int rr2 = 34 + (lane >> 1), half = lane & 1;
            float* dst = sub ? &S.V[rr2][half * 4] : &S.K[rr2][half * 4];
            *(float4*)dst = make_float4(0.f, 0.f, 0.f, 0.f);
        }
        int idxv = 0;
        if (lane < 17) idxv = idx[(size_t)row * 34 + sub * 17 + lane];
        float* Sb = &S.Q[0][0];
        #pragma unroll
        for (int rr = 0; rr < 5; rr++) {
            int e = rr * 4 + (lane >> 3);
            int p = lane & 7;
            // shfl executed by ALL lanes of the warp (source index wrapped);
            // only the load/store is guarded.
            int c = __shfl_sync(0xffffffffu, idxv, e & 31);
            if (e < 17) {
                int t = sub * 17 + e;
                float4 val = *(const float4*)&g_TAB[(size_t)(t * 14 + c) * 32 + p * 4];
                *(float4*)&Sb[(p >> 1) * 288 + t * 8 + (p & 1) * 4] = val;
            }
        }
    }
    __syncthreads();

    // ---- phase 3: warp = (row, head); lane i -> query t=i+2; lane 0 adds t=0,1 ----
    if (rowActive) {
        int h = sub, qb = 4 * h;
        attn_one(S, h, lane + 2);
        if (lane == 0) {
            *(float4*)&S.O[0][qb] = make_float4(S.V[0][qb + 0], S.V[0][qb + 1], S.V[0][qb + 2], 0.f);
            float4 q = *(const float4*)&S.Q[1][qb];
            float s0 = q.x * S.K[0][qb + 0] + q.y * S.K[0][qb + 1] + q.z * S.K[0][qb + 2];
            float s1 = q.x * S.K[1][qb + 0] + q.y * S.K[1][qb + 1] + q.z * S.K[1][qb + 2];
            float p0 = ex2f(s0), p1 = ex2f(s1);
            float inv = rcpf(p0 + p1);
            *(float4*)&S.O[1][qb] = make_float4(
                (p0 * S.V[0][qb + 0] + p1 * S.V[1][qb + 0]) * inv,
                (p0 * S.V[0][qb + 1] + p1 * S.V[1][qb + 1]) * inv,
                (p0 * S.V[0][qb + 2] + p1 * S.V[1][qb + 2]) * inv, 0.f);
        }
    }
    __syncthreads();

    int blockRows = nrows - blockIdx.x * RPB;
    if (blockRows > RPB) blockRows = RPB;

    // ---- phase 4: block-wide epilogue, 1 task per thread (3*34 = 102 <= 192) ----
    if (tid < blockRows * 34) {
        int rr = (tid >= 68) ? 2 : ((tid >= 34) ? 1 : 0);
        int t = tid - rr * 34;
        epilogue_pos(shm[rr], cw, t);
    }
    __syncthreads();

    // ---- phase 5: coalesced float4 store (119 float4 per row), div-free indexing ----
    float4* outv = (float4*)out;
    size_t outBase = (size_t)blockIdx.x * RPB * 119;
    int total4 = blockRows * 119;
    for (int i = tid; i < total4; i += THREADS) {
        int rr = (i >= 238) ? 2 : ((i >= 119) ? 1 : 0);
        int q = i - rr * 119;
        outv[outBase + (size_t)rr * 119 + q] = ((const float4*)&shm[rr].Q[0][0])[q];
    }
}

// ---------------- launch ----------------

extern "C" void kernel_launch(void* const* d_in, const int* in_sizes, int n_in,
                              void* d_out, int out_size)
{
    const int* idx         = (const int*)d_in[0];
    const float* tok_emb   = (const float*)d_in[1];
    const float* pos_params= (const float*)d_in[2];
    const float* z10_enc   = (const float*)d_in[3];
    const float* special   = (const float*)d_in[4];
    const float* wq        = (const float*)d_in[5];
    const float* wk        = (const float*)d_in[6];
    const float* wv        = (const float*)d_in[7];
    const float* wo        = (const float*)d_in[8];
    const float* ln1_g     = (const float*)d_in[9];
    const float* ln1_b     = (const float*)d_in[10];
    const float* ln2_g     = (const float*)d_in[11];
    const float* ln2_b     = (const float*)d_in[12];
    const float* lnf_g     = (const float*)d_in[13];
    const float* lnf_b     = (const float*)d_in[14];
    const float* ffn_w1    = (const float*)d_in[15];
    const float* ffn_b1    = (const float*)d_in[16];
    const float* ffn_w2    = (const float*)d_in[17];
    const float* ffn_b2    = (const float*)d_in[18];
    const float* head_w    = (const float*)d_in[19];

    int nrows = in_sizes[0] / 34;

    setup_kernel<<<1, 512>>>(tok_emb, pos_params, z10_enc, special,
                             wq, wk, wv, ln1_g, ln1_b,
                             wo, ln2_g, ln2_b, lnf_g, lnf_b,
                             ffn_w1, ffn_b1, ffn_w2, ffn_b2, head_w);

    int grid = (nrows + RPB - 1) / RPB;
    fwd_kernel<<<grid, THREADS>>>(idx, (float*)d_out, nrows);
}

// round 16
// speedup vs baseline: 1.1888x; 1.1888x over previous
#include <cuda_runtime.h>
#include <math.h>

#define RPB 3       // rows per block (2 warps per row: one per head)
#define THREADS 192

// ---------------- precomputed tables ----------------
// One 128B line per (t,c): 8 float4 parts:
//  p0=(q0,q1,q2,0) p1=(q3,q4,q5,0)
//  p2=(k0,k1,k2,0) p3=(k3,k4,k5,0)
//  p4=(v0,v1,v2,0) p5=(v3,v4,v5,0)
//  p6=(x0..x3)     p7=(x4,x5,0,0)
__device__ __align__(128) float g_TAB[34 * 14 * 32];
// Packed, 16B-aligned epilogue constants (200 floats = 50 float4)
__device__ __align__(16) float g_packed[200];

__device__ __forceinline__ int flatmap(int p) {
    if (p < 10) return p;
    if (p == 10) return 11;
    if (p < 21) return p - 11;
    if (p == 21) return 12;
    if (p < 33) { int z = p - 22; return z < 10 ? z : 10; }
    return 13;
}

__global__ void setup_kernel(const float* __restrict__ tok_emb, const float* __restrict__ pos_params,
                             const float* __restrict__ z10, const float* __restrict__ spec,
                             const float* __restrict__ wq, const float* __restrict__ wk,
                             const float* __restrict__ wv,
                             const float* __restrict__ ln1_g, const float* __restrict__ ln1_b,
                             const float* __restrict__ wo, const float* __restrict__ ln2_g,
                             const float* __restrict__ ln2_b,
                             const float* __restrict__ lnf_g, const float* __restrict__ lnf_b,
                             const float* __restrict__ fw1, const float* __restrict__ fb1,
                             const float* __restrict__ fw2, const float* __restrict__ fb2,
                             const float* __restrict__ head_w)
{
    int tid = threadIdx.x;

    if (tid < 200) {
        float v = 0.f;
        if (tid < 48) {
            int i = tid >> 3, j = tid & 7;
            v = (j < 6) ? wo[i * 6 + j] : 0.f;
        } else if (tid < 60) {
            int u = tid - 48; int j = u >> 1, m = u & 1;
            v = ln2_g[j] * fw1[j * 2 + m];
        } else if (tid < 62) {
            int m = tid - 60; float s = 0.f;
            for (int j = 0; j < 6; j++) s += ln2_g[j] * fw1[j * 2 + m];
            v = s;
        } else if (tid < 64) {
            int m = tid - 62; float s = fb1[m];
            for (int j = 0; j < 6; j++) s += ln2_b[j] * fw1[j * 2 + m];
            v = s;
        } else if (tid < 80) {
            int u = tid - 64; int m = u >> 3, j = u & 7;
            v = (j < 6) ? fw2[m * 6 + j] : 0.f;
        } else if (tid < 88) {
            int j = tid - 80;
            v = (j < 6) ? fb2[j] : 0.f;
        } else {
            int u = tid - 88; int n = u >> 3, j = u & 7;
            if (j < 6) {
                float W = head_w[j * 3 + 0] * tok_emb[n * 3 + 0]
                        + head_w[j * 3 + 1] * tok_emb[n * 3 + 1]
                        + head_w[j * 3 + 2] * tok_emb[n * 3 + 2];
                v = lnf_g[j] * W;
            } else {
                const float* gb = (j == 6) ? lnf_g : lnf_b;
                float s = 0.f;
                for (int jj = 0; jj < 6; jj++) {
                    float W = head_w[jj * 3 + 0] * tok_emb[n * 3 + 0]
                            + head_w[jj * 3 + 1] * tok_emb[n * 3 + 1]
                            + head_w[jj * 3 + 2] * tok_emb[n * 3 + 2];
                    s += gb[jj] * W;
                }
                v = s;
            }
        }
        g_packed[tid] = v;
    }

    for (int i = tid; i < 34 * 14; i += blockDim.x) {
        int t = i / 14, c = i % 14;
        int f = flatmap(t);
        float p0, p1, p2;
        if (f < 10) {
            float amp = pos_params[0], ph = pos_params[1], sl = pos_params[2], of = pos_params[3];
            float ang = 0.62831853071795864f * (float)f + ph;
            p0 = amp * cosf(ang);
            p1 = amp * sinf(ang);
            p2 = sl * (float)f + of;
        } else if (f == 10) {
            p0 = z10[0]; p1 = z10[1]; p2 = z10[2];
        } else {
            int s = f - 11;
            p0 = spec[s * 3 + 0]; p1 = spec[s * 3 + 1]; p2 = spec[s * 3 + 2];
        }
        float x[6] = { tok_emb[c * 3 + 0], tok_emb[c * 3 + 1], tok_emb[c * 3 + 2], p0, p1, p2 };
        float mu = 0.f;
        #pragma unroll
        for (int j = 0; j < 6; j++) mu += x[j];
        mu *= (1.f / 6.f);
        float var = 0.f;
        #pragma unroll
        for (int j = 0; j < 6; j++) { float d = x[j] - mu; var += d * d; }
        var *= (1.f / 6.f);
        float rs = rsqrtf(var + 1e-5f);
        float h[6];
        #pragma unroll
        for (int j = 0; j < 6; j++) h[j] = (x[j] - mu) * rs * ln1_g[j] + ln1_b[j];

        const float QS = 1.4426950408889634f / 1.7320508075688772f;  // log2(e)/sqrt(3)
        float qv[6], kv[6], vv[6];
        #pragma unroll
        for (int j = 0; j < 6; j++) {
            qv[j] = (h[3] * wq[j] + h[4] * wq[6 + j] + h[5] * wq[12 + j]) * QS;
            kv[j] =  h[3] * wk[j] + h[4] * wk[6 + j] + h[5] * wk[12 + j];
            vv[j] =  h[0] * wv[j] + h[1] * wv[6 + j] + h[2] * wv[12 + j];
        }
        float* T = &g_TAB[i * 32];
        T[0]  = qv[0]; T[1]  = qv[1]; T[2]  = qv[2]; T[3]  = 0.f;
        T[4]  = qv[3]; T[5]  = qv[4]; T[6]  = qv[5]; T[7]  = 0.f;
        T[8]  = kv[0]; T[9]  = kv[1]; T[10] = kv[2]; T[11] = 0.f;
        T[12] = kv[3]; T[13] = kv[4]; T[14] = kv[5]; T[15] = 0.f;
        T[16] = vv[0]; T[17] = vv[1]; T[18] = vv[2]; T[19] = 0.f;
        T[20] = vv[3]; T[21] = vv[4]; T[22] = vv[5]; T[23] = 0.f;
        T[24] = x[0];  T[25] = x[1];  T[26] = x[2];  T[27] = x[3];
        T[28] = x[4];  T[29] = x[5];  T[30] = 0.f;   T[31] = 0.f;
    }
}

// ---------------- main kernel ----------------

struct __align__(16) RowShm {
    float K[6][40];   // SoA keys, stride 40; cols 34..39 zeroed
    float V[6][40];   // SoA values
    float Q[34][8];   // [t][4h+0..2] = q for head h
    float X[34][8];   // [t][0..5]
    float O[34][8];   // [t][4h+0..2] = attention out head h
    // K+V region (480 floats) reused as the 476-float logits buffer in the epilogue
};

__device__ __forceinline__ float ex2f(float x) {
    float y;
    asm("ex2.approx.ftz.f32 %0, %1;" : "=f"(y) : "f"(x));
    return y;
}
__device__ __forceinline__ float rcpf(float x) {
    float y;
    asm("rcp.approx.ftz.f32 %0, %1;" : "=f"(y) : "f"(x));
    return y;
}
// Abramowitz-Stegun 7.1.26 erf approximation, |abs err| <= 1.5e-7
__device__ __forceinline__ float erf_fast(float x) {
    float ax = fabsf(x);
    float t = rcpf(1.f + 0.3275911f * ax);
    float y = t * (0.254829592f + t * (-0.284496736f + t * (1.421413741f
            + t * (-1.453152027f + t * 1.061405429f))));
    float e = ex2f(-1.4426950408889634f * ax * ax);
    float r = 1.f - y * e;
    return copysignf(r, x);
}

// Single causal-attention task for query t, head h; full blocks unmasked + one masked tail.
__device__ __forceinline__ void attn_one(RowShm& S, int h, int t) {
    int base = 3 * h, qb = 4 * h;
    float4 q = *(const float4*)&S.Q[t][qb];
    float l = 0.f, a0 = 0.f, a1 = 0.f, a2 = 0.f;
    int nbf = t >> 2;   // full 4-key blocks (no causal masking needed)
    #pragma unroll 1
    for (int b = 0; b < nbf; b++) {
        int k0 = b << 2;
        float4 kx = *(const float4*)&S.K[base + 0][k0];
        float4 ky = *(const float4*)&S.K[base + 1][k0];
        float4 kz = *(const float4*)&S.K[base + 2][k0];
        float4 vx = *(const float4*)&S.V[base + 0][k0];
        float4 vy = *(const float4*)&S.V[base + 1][k0];
        float4 vz = *(const float4*)&S.V[base + 2][k0];
        float p0 = ex2f(q.x * kx.x + q.y * ky.x + q.z * kz.x);
        float p1 = ex2f(q.x * kx.y + q.y * ky.y + q.z * kz.y);
        float p2 = ex2f(q.x * kx.z + q.y * ky.z + q.z * kz.z);
        float p3 = ex2f(q.x * kx.w + q.y * ky.w + q.z * kz.w);
        l  += (p0 + p1) + (p2 + p3);
        a0 += (p0 * vx.x + p1 * vx.y) + (p2 * vx.z + p3 * vx.w);
        a1 += (p0 * vy.x + p1 * vy.y) + (p2 * vy.z + p3 * vy.w);
        a2 += (p0 * vz.x + p1 * vz.y) + (p2 * vz.z + p3 * vz.w);
    }
    // masked tail block: keys 4*nbf .. t
    {
        int k0 = nbf << 2;
        int rem = t & 3;
        float4 kx = *(const float4*)&S.K[base + 0][k0];
        float4 ky = *(const float4*)&S.K[base + 1][k0];
        float4 kz = *(const float4*)&S.K[base + 2][k0];
        float4 vx = *(const float4*)&S.V[base + 0][k0];
        float4 vy = *(const float4*)&S.V[base + 1][k0];
        float4 vz = *(const float4*)&S.V[base + 2][k0];
        float p0 = ex2f(q.x * kx.x + q.y * ky.x + q.z * kz.x);
        float p1 = ex2f(q.x * kx.y + q.y * ky.y + q.z * kz.y);
        float p2 = ex2f(q.x * kx.z + q.y * ky.z + q.z * kz.z);
        float p3 = ex2f(q.x * kx.w + q.y * ky.w + q.z * kz.w);
        if (rem < 1) p1 = 0.f;
        if (rem < 2) p2 = 0.f;
        if (rem < 3) p3 = 0.f;
        l  += (p0 + p1) + (p2 + p3);
        a0 += (p0 * vx.x + p1 * vx.y) + (p2 * vx.z + p3 * vx.w);
        a1 += (p0 * vy.x + p1 * vy.y) + (p2 * vy.z + p3 * vy.w);
        a2 += (p0 * vz.x + p1 * vz.y) + (p2 * vz.z + p3 * vz.w);
    }
    float inv = rcpf(l);
    *(float4*)&S.O[t][qb] = make_float4(a0 * inv, a1 * inv, a2 * inv, 0.f);
}

// Per-position epilogue; constants read via float4, logits staged as float2 pairs.
__device__ __forceinline__ void epilogue_pos(RowShm& R, const float* cw, int t) {
    const float4* c4 = (const float4*)cw;
    float4 xa = *(const float4*)&R.X[t][0];
    float2 xb = *(const float2*)&R.X[t][4];
    float4 oa = *(const float4*)&R.O[t][0];
    float4 ob = *(const float4*)&R.O[t][4];
    float o[6] = { oa.x, oa.y, oa.z, ob.x, ob.y, ob.z };

    float y0 = xa.x, y1 = xa.y, y2 = xa.z, y3 = xa.w, y4 = xb.x, y5 = xb.y;
    #pragma unroll
    for (int i = 0; i < 6; i++) {
        float4 lo = c4[2 * i], hi = c4[2 * i + 1];
        y0 += o[i] * lo.x; y1 += o[i] * lo.y; y2 += o[i] * lo.z; y3 += o[i] * lo.w;
        y4 += o[i] * hi.x; y5 += o[i] * hi.y;
    }

    float mu = (y0 + y1 + y2 + y3 + y4 + y5) * (1.f / 6.f);
    float var = (y0 - mu) * (y0 - mu) + (y1 - mu) * (y1 - mu) + (y2 - mu) * (y2 - mu)
              + (y3 - mu) * (y3 - mu) + (y4 - mu) * (y4 - mu) + (y5 - mu) * (y5 - mu);
    float rs = rsqrtf(var * (1.f / 6.f) + 1e-5f);

    float4 fa = c4[12], fb = c4[13], fc = c4[14];
    float dot0 = y0 * fa.x + y1 * fa.z + y2 * fb.x + y3 * fb.z + y4 * fc.x + y5 * fc.z;
    float dot1 = y0 * fa.y + y1 * fa.w + y2 * fb.y + y3 * fb.w + y4 * fc.y + y5 * fc.w;
    float4 cb = c4[15];
    float f0 = rs * (dot0 - mu * cb.x) + cb.z;
    float f1 = rs * (dot1 - mu * cb.y) + cb.w;
    float g0 = 0.5f * f0 * (1.f + erf_fast(f0 * 0.70710678118654752f));
    float g1 = 0.5f * f1 * (1.f + erf_fast(f1 * 0.70710678118654752f));

    float4 r0lo = c4[16], r0hi = c4[17], r1lo = c4[18], r1hi = c4[19];
    float4 b2lo = c4[20], b2hi = c4[21];
    float z0 = y0 + g0 * r0lo.x + g1 * r1lo.x + b2lo.x;
    float z1 = y1 + g0 * r0lo.y + g1 * r1lo.y + b2lo.y;
    float z2 = y2 + g0 * r0lo.z + g1 * r1lo.z + b2lo.z;
    float z3 = y3 + g0 * r0lo.w + g1 * r1lo.w + b2lo.w;
    float z4 = y4 + g0 * r0hi.x + g1 * r1hi.x + b2hi.x;
    float z5 = y5 + g0 * r0hi.y + g1 * r1hi.y + b2hi.y;

    float mu2 = (z0 + z1 + z2 + z3 + z4 + z5) * (1.f / 6.f);
    float var2 = (z0 - mu2) * (z0 - mu2) + (z1 - mu2) * (z1 - mu2) + (z2 - mu2) * (z2 - mu2)
               + (z3 - mu2) * (z3 - mu2) + (z4 - mu2) * (z4 - mu2) + (z5 - mu2) * (z5 - mu2);
    float rs2 = rsqrtf(var2 * (1.f / 6.f) + 1e-5f);

    float2* Lp2 = (float2*)((float*)&R.K[0][0] + t * 14);
    #pragma unroll
    for (int n = 0; n < 14; n += 2) {
        float4 w0 = c4[22 + 2 * n], w1 = c4[23 + 2 * n];
        float4 u0 = c4[24 + 2 * n], u1 = c4[25 + 2 * n];
        float da = z0 * w0.x + z1 * w0.y + z2 * w0.z + z3 * w0.w + z4 * w1.x + z5 * w1.y;
        float db = z0 * u0.x + z1 * u0.y + z2 * u0.z + z3 * u0.w + z4 * u1.x + z5 * u1.y;
        float la = rs2 * (da - mu2 * w1.z) + w1.w;
        float lb = rs2 * (db - mu2 * u1.z) + u1.w;
        Lp2[n >> 1] = make_float2(la, lb);
    }
}

__global__ void __launch_bounds__(THREADS, 8)
fwd_kernel(const int* __restrict__ idx, float* __restrict__ out, int nrows)
{
    __shared__ RowShm shm[RPB];
    __shared__ __align__(16) float cw[200];

    int tid = threadIdx.x;
    for (int i = tid; i < 200; i += THREADS) cw[i] = g_packed[i];

    int w = tid >> 5, lane = tid & 31;
    int r = w >> 1;            // local row 0..RPB-1
    int sub = w & 1;           // head / gather-half
    int row = blockIdx.x * RPB + r;
    bool rowActive = row < nrows;
    RowShm& S = shm[r];

    // ---- phase 2: cooperative line-aligned gather into R13 SoA layout ----
    if (rowActive) {
        // zero K/V pad columns 34..39: sub0 -> K, sub1 -> V
        for (int i = lane; i < 36; i += 32) {
            int j = i / 6, tt = 34 + i % 6;
            if (sub == 0) S.K[j][tt] = 0.f; else S.V[j][tt] = 0.f;
        }
        int idxv = 0;
        if (lane < 17) idxv = idx[(size_t)row * 34 + sub * 17 + lane];
        int p = lane & 7;                       // part id, constant across rounds
        #pragma unroll
        for (int rr = 0; rr < 5; rr++) {
            int e = rr * 4 + (lane >> 3);       // entry within this warp's half
            int c = __shfl_sync(0xffffffffu, idxv, e & 31);   // executed by ALL lanes
            if (e < 17) {
                int t = sub * 17 + e;
                float4 val = *(const float4*)&g_TAB[(size_t)(t * 14 + c) * 32 + p * 4];
                if ((p & 6) == 0) {                    // p0,p1 -> Q[t][(p&1)*4 ..]
                    *(float4*)&S.Q[t][(p & 1) * 4] = val;
                } else if (p >= 6) {                   // p6,p7 -> X[t][(p&1)*4 ..]
                    *(float4*)&S.X[t][(p & 1) * 4] = val;
                } else {                               // p2..p5 -> K/V SoA scatter
                    float* A = (p < 4) ? &S.K[0][0] : &S.V[0][0];
                    int j0 = (p & 1) * 3;
                    A[(j0 + 0) * 40 + t] = val.x;
                    A[(j0 + 1) * 40 + t] = val.y;
                    A[(j0 + 2) * 40 + t] = val.z;
                }
            }
        }
    }
    __syncthreads();

    // ---- phase 3: warp = (row, head); lane i -> query t=i+2; lane 0 adds t=0,1 ----
    if (rowActive) {
        int h = sub, base = 3 * h, qb = 4 * h;
        attn_one(S, h, lane + 2);
        if (lane == 0) {
            *(float4*)&S.O[0][qb] = make_float4(S.V[base + 0][0], S.V[base + 1][0], S.V[base + 2][0], 0.f);
            float4 q = *(const float4*)&S.Q[1][qb];
            float s0 = q.x * S.K[base + 0][0] + q.y * S.K[base + 1][0] + q.z * S.K[base + 2][0];
            float s1 = q.x * S.K[base + 0][1] + q.y * S.K[base + 1][1] + q.z * S.K[base + 2][1];
            float p0 = ex2f(s0), p1 = ex2f(s1);
            float inv = rcpf(p0 + p1);
            *(float4*)&S.O[1][qb] = make_float4(
                (p0 * S.V[base + 0][0] + p1 * S.V[base + 0][1]) * inv,
                (p0 * S.V[base + 1][0] + p1 * S.V[base + 1][1]) * inv,
                (p0 * S.V[base + 2][0] + p1 * S.V[base + 2][1]) * inv, 0.f);
        }
    }
    __syncthreads();

    int blockRows = nrows - blockIdx.x * RPB;
    if (blockRows > RPB) blockRows = RPB;

    // ---- phase 4: block-wide epilogue, 1 task per thread (3*34 = 102 <= 192) ----
    if (tid < blockRows * 34) {
        int rr = (tid >= 68) ? 2 : ((tid >= 34) ? 1 : 0);
        int t = tid - rr * 34;
        epilogue_pos(shm[rr], cw, t);
    }
    __syncthreads();

    // ---- phase 5: coalesced float4 store (119 float4 per row), div-free indexing ----
    float4* outv = (float4*)out;
    size_t outBase = (size_t)blockIdx.x * RPB * 119;
    int total4 = blockRows * 119;
    for (int i = tid; i < total4; i += THREADS) {
        int rr = (i >= 238) ? 2 : ((i >= 119) ? 1 : 0);
        int q = i - rr * 119;
        outv[outBase + (size_t)rr * 119 + q] = ((const float4*)&shm[rr].K[0][0])[q];
    }
}

// ---------------- launch ----------------

extern "C" void kernel_launch(void* const* d_in, const int* in_sizes, int n_in,
                              void* d_out, int out_size)
{
    const int* idx         = (const int*)d_in[0];
    const float* tok_emb   = (const float*)d_in[1];
    const float* pos_params= (const float*)d_in[2];
    const float* z10_enc   = (const float*)d_in[3];
    const float* special   = (const float*)d_in[4];
    const float* wq        = (const float*)d_in[5];
    const float* wk        = (const float*)d_in[6];
    const float* wv        = (const float*)d_in[7];
    const float* wo        = (const float*)d_in[8];
    const float* ln1_g     = (const float*)d_in[9];
    const float* ln1_b     = (const float*)d_in[10];
    const float* ln2_g     = (const float*)d_in[11];
    const float* ln2_b     = (const float*)d_in[12];
    const float* lnf_g     = (const float*)d_in[13];
    const float* lnf_b     = (const float*)d_in[14];
    const float* ffn_w1    = (const float*)d_in[15];
    const float* ffn_b1    = (const float*)d_in[16];
    const float* ffn_w2    = (const float*)d_in[17];
    const float* ffn_b2    = (const float*)d_in[18];
    const float* head_w    = (const float*)d_in[19];

    int nrows = in_sizes[0] / 34;

    setup_kernel<<<1, 512>>>(tok_emb, pos_params, z10_enc, special,
                             wq, wk, wv, ln1_g, ln1_b,
                             wo, ln2_g, ln2_b, lnf_g, lnf_b,
                             ffn_w1, ffn_b1, ffn_w2, ffn_b2, head_w);

    int grid = (nrows + RPB - 1) / RPB;
    fwd_kernel<<<grid, THREADS>>>(idx, (float*)d_out, nrows);
}

// round 17
// speedup vs baseline: 1.2374x; 1.0409x over previous
#include <cuda_runtime.h>
#include <math.h>

#define RPB 3       // rows per block (2 warps per row: one per head)
#define THREADS 192

typedef unsigned long long u64;

// ---------------- precomputed tables ----------------
// Interleaved per (t,c): [0:6)=Q (pre-scaled by log2(e)/sqrt(3)), [6:12)=K, [12:18)=V, [18:24)=X
__device__ __align__(16) float g_TAB[34 * 14 * 24];
// Packed epilogue constants (224 floats):
//  [0:48)    wo padded rows of 8
//  [48:60)   fw1 folded w/ ln2_g, interleaved [j][m]
//  [60:64)   (cs1_0, cs1_1, b1c_0, b1c_1)
//  [64:80)   fw2 padded rows of 8
//  [80:88)   fb2 padded
//  [88:216)  transposed logit block, 8 rows of 16:
//            rows 0..5: Wt[j][n] = lnf_g[j]*W[n][j]  (n = 0..13, cols 14,15 = 0)
//            row 6: csf[n],  row 7: bf[n]
__device__ __align__(16) float g_packed[224];

__device__ __forceinline__ int flatmap(int p) {
    if (p < 10) return p;
    if (p == 10) return 11;
    if (p < 21) return p - 11;
    if (p == 21) return 12;
    if (p < 33) { int z = p - 22; return z < 10 ? z : 10; }
    return 13;
}

__global__ void setup_kernel(const float* __restrict__ tok_emb, const float* __restrict__ pos_params,
                             const float* __restrict__ z10, const float* __restrict__ spec,
                             const float* __restrict__ wq, const float* __restrict__ wk,
                             const float* __restrict__ wv,
                             const float* __restrict__ ln1_g, const float* __restrict__ ln1_b,
                             const float* __restrict__ wo, const float* __restrict__ ln2_g,
                             const float* __restrict__ ln2_b,
                             const float* __restrict__ lnf_g, const float* __restrict__ lnf_b,
                             const float* __restrict__ fw1, const float* __restrict__ fb1,
                             const float* __restrict__ fw2, const float* __restrict__ fb2,
                             const float* __restrict__ head_w)
{
    int tid = threadIdx.x;

    if (tid < 224) {
        float v = 0.f;
        if (tid < 48) {
            int i = tid >> 3, j = tid & 7;
            v = (j < 6) ? wo[i * 6 + j] : 0.f;
        } else if (tid < 60) {
            int u = tid - 48; int j = u >> 1, m = u & 1;
            v = ln2_g[j] * fw1[j * 2 + m];
        } else if (tid < 62) {
            int m = tid - 60; float s = 0.f;
            for (int j = 0; j < 6; j++) s += ln2_g[j] * fw1[j * 2 + m];
            v = s;
        } else if (tid < 64) {
            int m = tid - 62; float s = fb1[m];
            for (int j = 0; j < 6; j++) s += ln2_b[j] * fw1[j * 2 + m];
            v = s;
        } else if (tid < 80) {
            int u = tid - 64; int m = u >> 3, j = u & 7;
            v = (j < 6) ? fw2[m * 6 + j] : 0.f;
        } else if (tid < 88) {
            int j = tid - 80;
            v = (j < 6) ? fb2[j] : 0.f;
        } else if (tid < 216) {
            int u = tid - 88; int rowp = u >> 4, col = u & 15;
            if (col < 14) {
                int n = col;
                if (rowp < 6) {
                    int j = rowp;
                    float W = head_w[j * 3 + 0] * tok_emb[n * 3 + 0]
                            + head_w[j * 3 + 1] * tok_emb[n * 3 + 1]
                            + head_w[j * 3 + 2] * tok_emb[n * 3 + 2];
                    v = lnf_g[j] * W;
                } else {
                    const float* gb = (rowp == 6) ? lnf_g : lnf_b;
                    float s = 0.f;
                    for (int jj = 0; jj < 6; jj++) {
                        float W = head_w[jj * 3 + 0] * tok_emb[n * 3 + 0]
                                + head_w[jj * 3 + 1] * tok_emb[n * 3 + 1]
                                + head_w[jj * 3 + 2] * tok_emb[n * 3 + 2];
                        s += gb[jj] * W;
                    }
                    v = s;
                }
            }
        }
        g_packed[tid] = v;
    }

    for (int i = tid; i < 34 * 14; i += blockDim.x) {
        int t = i / 14, c = i % 14;
        int f = flatmap(t);
        float p0, p1, p2;
        if (f < 10) {
            float amp = pos_params[0], ph = pos_params[1], sl = pos_params[2], of = pos_params[3];
            float ang = 0.62831853071795864f * (float)f + ph;
            p0 = amp * cosf(ang);
            p1 = amp * sinf(ang);
            p2 = sl * (float)f + of;
        } else if (f == 10) {
            p0 = z10[0]; p1 = z10[1]; p2 = z10[2];
        } else {
            int s = f - 11;
            p0 = spec[s * 3 + 0]; p1 = spec[s * 3 + 1]; p2 = spec[s * 3 + 2];
        }
        float x[6] = { tok_emb[c * 3 + 0], tok_emb[c * 3 + 1], tok_emb[c * 3 + 2], p0, p1, p2 };
        float mu = 0.f;
        #pragma unroll
        for (int j = 0; j < 6; j++) mu += x[j];
        mu *= (1.f / 6.f);
        float var = 0.f;
        #pragma unroll
        for (int j = 0; j < 6; j++) { float d = x[j] - mu; var += d * d; }
        var *= (1.f / 6.f);
        float rs = rsqrtf(var + 1e-5f);
        float h[6];
        #pragma unroll
        for (int j = 0; j < 6; j++) h[j] = (x[j] - mu) * rs * ln1_g[j] + ln1_b[j];

        const float QS = 1.4426950408889634f / 1.7320508075688772f;  // log2(e)/sqrt(3)
        float* T = &g_TAB[i * 24];
        #pragma unroll
        for (int j = 0; j < 6; j++) {
            float q  = h[3] * wq[j] + h[4] * wq[6 + j] + h[5] * wq[12 + j];
            float k  = h[3] * wk[j] + h[4] * wk[6 + j] + h[5] * wk[12 + j];
            float vv = h[0] * wv[j] + h[1] * wv[6 + j] + h[2] * wv[12 + j];
            T[j]      = q * QS;
            T[6 + j]  = k;
            T[12 + j] = vv;
            T[18 + j] = x[j];
        }
    }
}

// ---------------- packed f32x2 helpers ----------------

__device__ __forceinline__ u64 pk(float lo, float hi) {
    u64 r;
    asm("mov.b64 %0, {%1, %2};" : "=l"(r) : "f"(lo), "f"(hi));
    return r;
}
__device__ __forceinline__ void upk(float& lo, float& hi, u64 v) {
    asm("mov.b64 {%0, %1}, %2;" : "=f"(lo), "=f"(hi) : "l"(v));
}
__device__ __forceinline__ u64 fma2(u64 a, u64 b, u64 c) {
    u64 r;
    asm("fma.rn.f32x2 %0, %1, %2, %3;" : "=l"(r) : "l"(a), "l"(b), "l"(c));
    return r;
}
__device__ __forceinline__ u64 mul2(u64 a, u64 b) {
    u64 r;
    asm("mul.rn.f32x2 %0, %1, %2;" : "=l"(r) : "l"(a), "l"(b));
    return r;
}
__device__ __forceinline__ u64 add2(u64 a, u64 b) {
    u64 r;
    asm("add.rn.f32x2 %0, %1, %2;" : "=l"(r) : "l"(a), "l"(b));
    return r;
}
__device__ __forceinline__ u64 d2u_lo(double2 d) { return __double_as_longlong(d.x); }
__device__ __forceinline__ u64 d2u_hi(double2 d) { return __double_as_longlong(d.y); }

// ---------------- main kernel ----------------

struct __align__(16) RowShm {
    float K[6][40];   // SoA keys, stride 40; cols 34..39 zeroed
    float V[6][40];   // SoA values
    float Q[34][8];   // [t][4h+0..2] = q for head h
    float X[34][8];   // [t][0..5]
    float O[34][8];   // [t][4h+0..2] = attention out head h
    // K+V region (480 floats) reused as the 476-float logits buffer in the epilogue
};

__device__ __forceinline__ float ex2f(float x) {
    float y;
    asm("ex2.approx.ftz.f32 %0, %1;" : "=f"(y) : "f"(x));
    return y;
}
__device__ __forceinline__ float rcpf(float x) {
    float y;
    asm("rcp.approx.ftz.f32 %0, %1;" : "=f"(y) : "f"(x));
    return y;
}
// Abramowitz-Stegun 7.1.26 erf approximation, |abs err| <= 1.5e-7
__device__ __forceinline__ float erf_fast(float x) {
    float ax = fabsf(x);
    float t = rcpf(1.f + 0.3275911f * ax);
    float y = t * (0.254829592f + t * (-0.284496736f + t * (1.421413741f
            + t * (-1.453152027f + t * 1.061405429f))));
    float e = ex2f(-1.4426950408889634f * ax * ax);
    float r = 1.f - y * e;
    return copysignf(r, x);
}

// Single causal-attention task for query t, head h; packed f32x2 math.
__device__ __forceinline__ void attn_one(RowShm& S, int h, int t) {
    int base = 3 * h, qb = 4 * h;
    float4 q = *(const float4*)&S.Q[t][qb];
    u64 qx = pk(q.x, q.x), qy = pk(q.y, q.y), qz = pk(q.z, q.z);
    u64 A0 = 0ull, A1 = 0ull, A2 = 0ull, L = 0ull;
    int nbf = t >> 2;   // full 4-key blocks (no masking)
    #pragma unroll 1
    for (int b = 0; b < nbf; b++) {
        int k0 = b << 2;
        double2 kxd = *(const double2*)&S.K[base + 0][k0];
        double2 kyd = *(const double2*)&S.K[base + 1][k0];
        double2 kzd = *(const double2*)&S.K[base + 2][k0];
        u64 s01 = fma2(qz, d2u_lo(kzd), fma2(qy, d2u_lo(kyd), mul2(qx, d2u_lo(kxd))));
        u64 s23 = fma2(qz, d2u_hi(kzd), fma2(qy, d2u_hi(kyd), mul2(qx, d2u_hi(kxd))));
        float s0, s1, s2, s3;
        upk(s0, s1, s01);
        upk(s2, s3, s23);
        u64 p01 = pk(ex2f(s0), ex2f(s1));
        u64 p23 = pk(ex2f(s2), ex2f(s3));
        double2 vxd = *(const double2*)&S.V[base + 0][k0];
        double2 vyd = *(const double2*)&S.V[base + 1][k0];
        double2 vzd = *(const double2*)&S.V[base + 2][k0];
        L  = add2(L, add2(p01, p23));
        A0 = fma2(p01, d2u_lo(vxd), A0);
        A0 = fma2(p23, d2u_hi(vxd), A0);
        A1 = fma2(p01, d2u_lo(vyd), A1);
        A1 = fma2(p23, d2u_hi(vyd), A1);
        A2 = fma2(p01, d2u_lo(vzd), A2);
        A2 = fma2(p23, d2u_hi(vzd), A2);
    }
    // masked tail block: keys 4*nbf .. t (pad columns are zeroed)
    {
        int k0 = nbf << 2;
        int rem = t & 3;
        double2 kxd = *(const double2*)&S.K[base + 0][k0];
        double2 kyd = *(const double2*)&S.K[base + 1][k0];
        double2 kzd = *(const double2*)&S.K[base + 2][k0];
        u64 s01 = fma2(qz, d2u_lo(kzd), fma2(qy, d2u_lo(kyd), mul2(qx, d2u_lo(kxd))));
        u64 s23 = fma2(qz, d2u_hi(kzd), fma2(qy, d2u_hi(kyd), mul2(qx, d2u_hi(kxd))));
        float s0, s1, s2, s3;
        upk(s0, s1, s01);
        upk(s2, s3, s23);
        float p0 = ex2f(s0);
        float p1 = ex2f(s1); if (rem < 1) p1 = 0.f;
        float p2 = ex2f(s2); if (rem < 2) p2 = 0.f;
        float p3 = ex2f(s3); if (rem < 3) p3 = 0.f;
        u64 p01 = pk(p0, p1), p23 = pk(p2, p3);
        double2 vxd = *(const double2*)&S.V[base + 0][k0];
        double2 vyd = *(const double2*)&S.V[base + 1][k0];
        double2 vzd = *(const double2*)&S.V[base + 2][k0];
        L  = add2(L, add2(p01, p23));
        A0 = fma2(p01, d2u_lo(vxd), A0);
        A0 = fma2(p23, d2u_hi(vxd), A0);
        A1 = fma2(p01, d2u_lo(vyd), A1);
        A1 = fma2(p23, d2u_hi(vyd), A1);
        A2 = fma2(p01, d2u_lo(vzd), A2);
        A2 = fma2(p23, d2u_hi(vzd), A2);
    }
    float l0, l1, a00, a01, a10, a11, a20, a21;
    upk(l0, l1, L);
    upk(a00, a01, A0);
    upk(a10, a11, A1);
    upk(a20, a21, A2);
    float inv = rcpf(l0 + l1);
    *(float4*)&S.O[t][qb] = make_float4((a00 + a01) * inv, (a10 + a11) * inv, (a20 + a21) * inv, 0.f);
}

// Per-position epilogue; o@wo and logit matmul in packed f32x2.
__device__ __forceinline__ void epilogue_pos(RowShm& R, const float* cw, int t) {
    const float4* c4 = (const float4*)cw;
    double2 x01d = *(const double2*)&R.X[t][0];   // pairs (x0,x1),(x2,x3)
    double2 x45d = *(const double2*)&R.X[t][4];   // (x4,x5),(pad)
    float4 oa = *(const float4*)&R.O[t][0];
    float4 ob = *(const float4*)&R.O[t][4];
    float o[6] = { oa.x, oa.y, oa.z, ob.x, ob.y, ob.z };

    u64 y01 = d2u_lo(x01d), y23 = d2u_hi(x01d), y45 = d2u_lo(x45d);
    #pragma unroll
    for (int i = 0; i < 6; i++) {
        u64 os = pk(o[i], o[i]);
        double2 wl = *(const double2*)&cw[i * 8];       // (w0,w1),(w2,w3)
        u64 wh = *(const u64*)&cw[i * 8 + 4];           // (w4,w5)
        y01 = fma2(os, d2u_lo(wl), y01);
        y23 = fma2(os, d2u_hi(wl), y23);
        y45 = fma2(os, wh, y45);
    }
    float y0, y1, y2, y3, y4, y5;
    upk(y0, y1, y01);
    upk(y2, y3, y23);
    upk(y4, y5, y45);

    float mu = (y0 + y1 + y2 + y3 + y4 + y5) * (1.f / 6.f);
    float var = (y0 - mu) * (y0 - mu) + (y1 - mu) * (y1 - mu) + (y2 - mu) * (y2 - mu)
              + (y3 - mu) * (y3 - mu) + (y4 - mu) * (y4 - mu) + (y5 - mu) * (y5 - mu);
    float rs = rsqrtf(var * (1.f / 6.f) + 1e-5f);

    float4 fa = c4[12], fb = c4[13], fc = c4[14];
    float dot0 = y0 * fa.x + y1 * fa.z + y2 * fb.x + y3 * fb.z + y4 * fc.x + y5 * fc.z;
    float dot1 = y0 * fa.y + y1 * fa.w + y2 * fb.y + y3 * fb.w + y4 * fc.y + y5 * fc.w;
    float4 cb = c4[15];
    float f0 = rs * (dot0 - mu * cb.x) + cb.z;
    float f1 = rs * (dot1 - mu * cb.y) + cb.w;
    float g0 = 0.5f * f0 * (1.f + erf_fast(f0 * 0.70710678118654752f));
    float g1 = 0.5f * f1 * (1.f + erf_fast(f1 * 0.70710678118654752f));

    float4 r0lo = c4[16], r0hi = c4[17], r1lo = c4[18], r1hi = c4[19];
    float4 b2lo = c4[20], b2hi = c4[21];
    float z0 = y0 + g0 * r0lo.x + g1 * r1lo.x + b2lo.x;
    float z1 = y1 + g0 * r0lo.y + g1 * r1lo.y + b2lo.y;
    float z2 = y2 + g0 * r0lo.z + g1 * r1lo.z + b2lo.z;
    float z3 = y3 + g0 * r0lo.w + g1 * r1lo.w + b2lo.w;
    float z4 = y4 + g0 * r0hi.x + g1 * r1hi.x + b2hi.x;
    float z5 = y5 + g0 * r0hi.y + g1 * r1hi.y + b2hi.y;

    float mu2 = (z0 + z1 + z2 + z3 + z4 + z5) * (1.f / 6.f);
    float var2 = (z0 - mu2) * (z0 - mu2) + (z1 - mu2) * (z1 - mu2) + (z2 - mu2) * (z2 - mu2)
               + (z3 - mu2) * (z3 - mu2) + (z4 - mu2) * (z4 - mu2) + (z5 - mu2) * (z5 - mu2);
    float rs2 = rsqrtf(var2 * (1.f / 6.f) + 1e-5f);

    // packed logits: transposed weight rows of 16 floats starting at cw[88]
    u64 zs0 = pk(z0, z0), zs1 = pk(z1, z1), zs2 = pk(z2, z2);
    u64 zs3 = pk(z3, z3), zs4 = pk(z4, z4), zs5 = pk(z5, z5);
    u64 nmu = pk(-mu2, -mu2), rsp = pk(rs2, rs2);
    u64* Lp = (u64*)((float*)&R.K[0][0] + t * 14);
    #pragma unroll
    for (int g = 0; g < 4; g++) {   // g covers logit pairs 2g, 2g+1 (g=3: only 2g valid)
        double2 w0 = *(const double2*)&cw[88  + 4 * g];
        double2 w1 = *(const double2*)&cw[104 + 4 * g];
        double2 w2 = *(const double2*)&cw[120 + 4 * g];
        double2 w3 = *(const double2*)&cw[136 + 4 * g];
        double2 w4 = *(const double2*)&cw[152 + 4 * g];
        double2 w5 = *(const double2*)&cw[168 + 4 * g];
        double2 cs = *(const double2*)&cw[184 + 4 * g];
        double2 bf = *(const double2*)&cw[200 + 4 * g];
        u64 dA = mul2(zs0, d2u_lo(w0));
        dA = fma2(zs1, d2u_lo(w1), dA);
        dA = fma2(zs2, d2u_lo(w2), dA);
        dA = fma2(zs3, d2u_lo(w3), dA);
        dA = fma2(zs4, d2u_lo(w4), dA);
        dA = fma2(zs5, d2u_lo(w5), dA);
        dA = fma2(nmu, d2u_lo(cs), dA);
        Lp[2 * g] = fma2(rsp, dA, d2u_lo(bf));
        if (g < 3) {
            u64 dB = mul2(zs0, d2u_hi(w0));
            dB = fma2(zs1, d2u_hi(w1), dB);
            dB = fma2(zs2, d2u_hi(w2), dB);
            dB = fma2(zs3, d2u_hi(w3), dB);
            dB = fma2(zs4, d2u_hi(w4), dB);
            dB = fma2(zs5, d2u_hi(w5), dB);
            dB = fma2(nmu, d2u_hi(cs), dB);
            Lp[2 * g + 1] = fma2(rsp, dB, d2u_hi(bf));
        }
    }
}

__global__ void __launch_bounds__(THREADS, 7)
fwd_kernel(const int* __restrict__ idx, float* __restrict__ out, int nrows)
{
    __shared__ RowShm shm[RPB];
    __shared__ __align__(16) float cw[224];

    int tid = threadIdx.x;
    for (int i = tid; i < 224; i += THREADS) cw[i] = g_packed[i];

    int w = tid >> 5, lane = tid & 31;
    int r = w >> 1;            // local row 0..RPB-1
    int sub = w & 1;           // head / gather-half
    int row = blockIdx.x * RPB + r;
    bool rowActive = row < nrows;
    RowShm& S = shm[r];

    // ---- phase 2: two warps gather one row (17 positions each) ----
    if (rowActive) {
        for (int i = lane; i < 36; i += 32) {   // zero pad cols: sub0 -> K, sub1 -> V
            int j = i / 6, tt = 34 + i % 6;
            if (sub == 0) S.K[j][tt] = 0.f; else S.V[j][tt] = 0.f;
        }
        if (lane < 17) {
            int t = sub * 17 + lane;
            int c = idx[(size_t)row * 34 + t];
            const float4* Tp = (const float4*)&g_TAB[(t * 14 + c) * 24];
            float4 v0 = Tp[0], v1 = Tp[1], v2 = Tp[2], v3 = Tp[3], v4 = Tp[4], v5 = Tp[5];
            *(float4*)&S.Q[t][0] = make_float4(v0.x, v0.y, v0.z, 0.f);
            *(float4*)&S.Q[t][4] = make_float4(v0.w, v1.x, v1.y, 0.f);
            S.K[0][t] = v1.z; S.K[1][t] = v1.w; S.K[2][t] = v2.x;
            S.K[3][t] = v2.y; S.K[4][t] = v2.z; S.K[5][t] = v2.w;
            S.V[0][t] = v3.x; S.V[1][t] = v3.y; S.V[2][t] = v3.z;
            S.V[3][t] = v3.w; S.V[4][t] = v4.x; S.V[5][t] = v4.y;
            *(float4*)&S.X[t][0] = make_float4(v4.z, v4.w, v5.x, v5.y);
            *(float2*)&S.X[t][4] = make_float2(v5.z, v5.w);
        }
    }
    __syncthreads();

    // ---- phase 3: warp = (row, head); lane i -> query t=i+2; lane 0 adds t=0,1 ----
    if (rowActive) {
        int h = sub, base = 3 * h, qb = 4 * h;
        attn_one(S, h, lane + 2);
        if (lane == 0) {
            *(float4*)&S.O[0][qb] = make_float4(S.V[base + 0][0], S.V[base + 1][0], S.V[base + 2][0], 0.f);
            float4 q = *(const float4*)&S.Q[1][qb];
            float s0 = q.x * S.K[base + 0][0] + q.y * S.K[base + 1][0] + q.z * S.K[base + 2][0];
            float s1 = q.x * S.K[base + 0][1] + q.y * S.K[base + 1][1] + q.z * S.K[base + 2][1];
            float p0 = ex2f(s0), p1 = ex2f(s1);
            float inv = rcpf(p0 + p1);
            *(float4*)&S.O[1][qb] = make_float4(
                (p0 * S.V[base + 0][0] + p1 * S.V[base + 0][1]) * inv,
                (p0 * S.V[base + 1][0] + p1 * S.V[base + 1][1]) * inv,
                (p0 * S.V[base + 2][0] + p1 * S.V[base + 2][1]) * inv, 0.f);
        }
    }
    __syncthreads();

    int blockRows = nrows - blockIdx.x * RPB;
    if (blockRows > RPB) blockRows = RPB;

    // ---- phase 4: block-wide epilogue, 1 task per thread (3*34 = 102 <= 192) ----
    if (tid < blockRows * 34) {
        int rr = (tid >= 68) ? 2 : ((tid >= 34) ? 1 : 0);
        int t = tid - rr * 34;
        epilogue_pos(shm[rr], cw, t);
    }
    __syncthreads();

    // ---- phase 5: coalesced float4 store (119 float4 per row), div-free indexing ----
    float4* outv = (float4*)out;
    size_t outBase = (size_t)blockIdx.x * RPB * 119;
    int total4 = blockRows * 119;
    for (int i = tid; i < total4; i += THREADS) {
        int rr = (i >= 238) ? 2 : ((i >= 119) ? 1 : 0);
        int q = i - rr * 119;
        outv[outBase + (size_t)rr * 119 + q] = ((const float4*)&shm[rr].K[0][0])[q];
    }
}

// ---------------- launch ----------------

extern "C" void kernel_launch(void* const* d_in, const int* in_sizes, int n_in,
                              void* d_out, int out_size)
{
    const int* idx         = (const int*)d_in[0];
    const float* tok_emb   = (const float*)d_in[1];
    const float* pos_params= (const float*)d_in[2];
    const float* z10_enc   = (const float*)d_in[3];
    const float* special   = (const float*)d_in[4];
    const float* wq        = (const float*)d_in[5];
    const float* wk        = (const float*)d_in[6];
    const float* wv        = (const float*)d_in[7];
    const float* wo        = (const float*)d_in[8];
    const float* ln1_g     = (const float*)d_in[9];
    const float* ln1_b     = (const float*)d_in[10];
    const float* ln2_g     = (const float*)d_in[11];
    const float* ln2_b     = (const float*)d_in[12];
    const float* lnf_g     = (const float*)d_in[13];
    const float* lnf_b     = (const float*)d_in[14];
    const float* ffn_w1    = (const float*)d_in[15];
    const float* ffn_b1    = (const float*)d_in[16];
    const float* ffn_w2    = (const float*)d_in[17];
    const float* ffn_b2    = (const float*)d_in[18];
    const float* head_w    = (const float*)d_in[19];

    int nrows = in_sizes[0] / 34;

    setup_kernel<<<1, 512>>>(tok_emb, pos_params, z10_enc, special,
                             wq, wk, wv, ln1_g, ln1_b,
                             wo, ln2_g, ln2_b, lnf_g, lnf_b,
                             ffn_w1, ffn_b1, ffn_w2, ffn_b2, head_w);

    int grid = (nrows + RPB - 1) / RPB;
    fwd_kernel<<<grid, THREADS>>>(idx, (float*)d_out, nrows);
}